// round 6
// baseline (speedup 1.0000x reference)
#include <cuda_runtime.h>
#include <math.h>

#define B_  8
#define T_  8192
#define F_  64
#define M_  128          // omega rows
#define MM2 256          // feature dim = 2*M
#define D_  64
#define DP_ 65           // D + 1 (normalizer column)

#define KV_CH    37      // kv chunks -> grid 37*8 = 296 = exactly 2 waves of 148
#define KV_ROWS  224     // rows per chunk (37*224 = 8288 >= 8192, tail masked)

constexpr float kEPS   = 1e-9f;
constexpr float kSCALE = 0.0625f;  // 1/sqrt(2*128) = 1/16

// ---------------- device scratch (static, allocation-free) ----------------
// d-major partials: g_kvp[(cx*B+b)*DP*MM2 + d*MM2 + m]
__device__ float g_kvp[(size_t)KV_CH * B_ * DP_ * MM2];    // 19.7 MB
__device__ float g_kv [(size_t)B_ * DP_ * MM2];            // 0.53 MB

// ======================= Stage 1: kv_fused (phi_k + kv) =======================
// grid (KV_CH, B), block 512. Per 32-row step:
//   stage K/V rows -> phi GEMM (warp owns m-octet, lane owns row; omega loads
//   are warp-broadcast LDS.128) -> accumulate (2 threads per feature, 32+1 accs).
#define KVF_WT   0                         // [64][132] omega^T padded
#define KVF_XS   (64 * 132)                // [32][68]
#define KVF_VS   (KVF_XS + 32 * 68)        // [32][68]
#define KVF_PHI  (KVF_VS + 32 * 68)        // [32][260]
#define KVF_SS   (KVF_PHI + 32 * 260)      // [32]
#define KVF_SMEM ((KVF_SS + 32) * 4)       // 84,608 B

__global__ void __launch_bounds__(512) kv_fused(const float* __restrict__ key,
                                                const float* __restrict__ value,
                                                const float* __restrict__ omega)
{
    extern __shared__ float sm[];
    float* wT   = sm + KVF_WT;
    float* xs   = sm + KVF_XS;
    float* vs   = sm + KVF_VS;
    float* phis = sm + KVF_PHI;
    float* ss   = sm + KVF_SS;

    const int b    = blockIdx.y;
    const int cx   = blockIdx.x;
    const int s0   = cx * KV_ROWS;
    const int tid  = threadIdx.x;
    const int w    = tid >> 5;     // warp 0..15 -> m-octet w*8
    const int lane = tid & 31;     // row within tile

    // load omega transposed: wT[f][m], stride 132 (one-time)
    #pragma unroll
    for (int i = 0; i < 16; i++) {
        int idx = tid + 512 * i;               // 8192 floats, omega[m][f]
        wT[(idx & 63) * 132 + (idx >> 6)] = omega[idx];
    }

    float acc[32];
    float accn = 0.f;
    #pragma unroll
    for (int d = 0; d < 32; d++) acc[d] = 0.f;

    const int m    = tid >> 1;     // feature 0..255 (accumulate phase)
    const int half = tid & 1;      // d-column half
    const int lr   = tid >> 4;     // staging row 0..31
    const int lc   = tid & 15;     // staging float4 col

    for (int sb = 0; sb < KV_ROWS; sb += 32) {
        const int sg = s0 + sb;
        __syncthreads();                       // prev accumulate done

        // ---- stage 32 key rows + 32 value rows; ss via 16-lane shfl ----
        {
            const int r = sg + lr;
            float4 xv = make_float4(0.f, 0.f, 0.f, 0.f);
            float4 vv = make_float4(0.f, 0.f, 0.f, 0.f);
            if (r < T_) {
                xv = *reinterpret_cast<const float4*>(key   + ((size_t)b * T_ + r) * F_ + lc * 4);
                vv = *reinterpret_cast<const float4*>(value + ((size_t)b * T_ + r) * D_ + lc * 4);
            }
            *reinterpret_cast<float4*>(&xs[lr * 68 + lc * 4]) = xv;
            *reinterpret_cast<float4*>(&vs[lr * 68 + lc * 4]) = vv;
            float p = xv.x * xv.x + xv.y * xv.y + xv.z * xv.z + xv.w * xv.w;
            p += __shfl_xor_sync(0xffffffffu, p, 8);
            p += __shfl_xor_sync(0xffffffffu, p, 4);
            p += __shfl_xor_sync(0xffffffffu, p, 2);
            p += __shfl_xor_sync(0xffffffffu, p, 1);
            if (lc == 0) ss[lr] = 0.5f * p;
        }
        __syncthreads();

        // ---- phi GEMM: warp w -> m cols w*8..w*8+7, lane -> row ----
        {
            float a[8];
            #pragma unroll
            for (int c = 0; c < 8; c++) a[c] = 0.f;

            const float* xrow = &xs[lane * 68];
            #pragma unroll
            for (int f0 = 0; f0 < 64; f0 += 4) {
                float4 xv = *reinterpret_cast<const float4*>(&xrow[f0]);
                #pragma unroll
                for (int i = 0; i < 4; i++) {
                    const float* wr = &wT[(f0 + i) * 132 + w * 8];
                    float4 wa = *reinterpret_cast<const float4*>(wr);       // broadcast
                    float4 wb = *reinterpret_cast<const float4*>(wr + 4);   // broadcast
                    float xf = (i == 0) ? xv.x : (i == 1) ? xv.y : (i == 2) ? xv.z : xv.w;
                    a[0] += xf * wa.x; a[1] += xf * wa.y;
                    a[2] += xf * wa.z; a[3] += xf * wa.w;
                    a[4] += xf * wb.x; a[5] += xf * wb.y;
                    a[6] += xf * wb.z; a[7] += xf * wb.w;
                }
            }

            float s  = ss[lane];
            float sc = (sg + lane < T_) ? kSCALE : 0.f;
            float4 p1a, p1b, p2a, p2b;
            p1a.x = (__expf( a[0] - s) + kEPS) * sc;
            p1a.y = (__expf( a[1] - s) + kEPS) * sc;
            p1a.z = (__expf( a[2] - s) + kEPS) * sc;
            p1a.w = (__expf( a[3] - s) + kEPS) * sc;
            p1b.x = (__expf( a[4] - s) + kEPS) * sc;
            p1b.y = (__expf( a[5] - s) + kEPS) * sc;
            p1b.z = (__expf( a[6] - s) + kEPS) * sc;
            p1b.w = (__expf( a[7] - s) + kEPS) * sc;
            p2a.x = (__expf(-a[0] - s) + kEPS) * sc;
            p2a.y = (__expf(-a[1] - s) + kEPS) * sc;
            p2a.z = (__expf(-a[2] - s) + kEPS) * sc;
            p2a.w = (__expf(-a[3] - s) + kEPS) * sc;
            p2b.x = (__expf(-a[4] - s) + kEPS) * sc;
            p2b.y = (__expf(-a[5] - s) + kEPS) * sc;
            p2b.z = (__expf(-a[6] - s) + kEPS) * sc;
            p2b.w = (__expf(-a[7] - s) + kEPS) * sc;
            float* pr = &phis[lane * 260 + w * 8];
            *reinterpret_cast<float4*>(pr)           = p1a;
            *reinterpret_cast<float4*>(pr + 4)       = p1b;
            *reinterpret_cast<float4*>(pr + 128)     = p2a;
            *reinterpret_cast<float4*>(pr + 132)     = p2b;
        }
        __syncthreads();

        // ---- accumulate: 2 threads per feature m, 32 d-cols each ----
        const float* vbase = &vs[half * 32];
        #pragma unroll 4
        for (int j = 0; j < 32; j++) {
            float ph = phis[j * 260 + m];
            const float* vr = &vbase[j * 68];
            #pragma unroll
            for (int q = 0; q < 8; q++) {
                float4 vv = *reinterpret_cast<const float4*>(&vr[q * 4]);
                acc[q * 4 + 0] += ph * vv.x;
                acc[q * 4 + 1] += ph * vv.y;
                acc[q * 4 + 2] += ph * vv.z;
                acc[q * 4 + 3] += ph * vv.w;
            }
            accn += ph;   // normalizer (kept by half==1)
        }
    }

    // write d-major partials: coalesced over m for each d
    float* base = g_kvp + ((size_t)(cx * B_ + b)) * DP_ * MM2 + m;
    #pragma unroll
    for (int d = 0; d < 32; d++) base[(half * 32 + d) * MM2] = acc[d];
    if (half == 1) base[64 * MM2] = accn;
}

// ======================= Stage 2: reduce partials (float4) =======================
#define KV_N4 (B_ * DP_ * MM2 / 4)   // 33280

__global__ void __launch_bounds__(256) reduce_kv()
{
    int i = blockIdx.x * blockDim.x + threadIdx.x;
    if (i < KV_N4) {
        const float4* src = reinterpret_cast<const float4*>(g_kvp);
        float4 s = make_float4(0.f, 0.f, 0.f, 0.f);
        #pragma unroll
        for (int c = 0; c < KV_CH; c++) {
            float4 v = src[(size_t)c * KV_N4 + i];
            s.x += v.x; s.y += v.y; s.z += v.z; s.w += v.w;
        }
        reinterpret_cast<float4*>(g_kv)[i] = s;
    }
}

// ======================= Stage 3: qkv_fused (phi_q + qkv + normalize) =======================
// grid (T/64, B), block 512. Phase A: phi_q (warp -> m-octet over all 64 rows,
// lane -> rows lane, lane+32). Phase B: thread (tt = tid>>3, p = tid&7) owns 8 cols.
#define QF_KVS  0                          // [256][68]  kv as [m][d]
#define QF_WT   (256 * 68)                 // [64][132]
#define QF_XS   (QF_WT + 64 * 132)         // [64][68]
#define QF_PHI  (QF_XS + 64 * 68)          // [64][260]
#define QF_SS   (QF_PHI + 64 * 260)        // [64]
#define QF_NRM  (QF_SS + 64)               // [64]
#define QF_SMEM ((QF_NRM + 64) * 4)        // 187,904 B

__global__ void __launch_bounds__(512) qkv_fused(const float* __restrict__ query,
                                                 const float* __restrict__ omega,
                                                 float* __restrict__ out)
{
    extern __shared__ float sm[];
    float* kvs  = sm + QF_KVS;
    float* wT   = sm + QF_WT;
    float* xs   = sm + QF_XS;
    float* phis = sm + QF_PHI;
    float* ss   = sm + QF_SS;
    float* norm = sm + QF_NRM;

    const int b    = blockIdx.y;
    const int t0   = blockIdx.x * 64;
    const int tid  = threadIdx.x;
    const int w    = tid >> 5;
    const int lane = tid & 31;

    // ---- loads: kv (d-major global -> [m][d] smem), omega^T, query tile ----
    {
        const float* kvg = g_kv + (size_t)b * DP_ * MM2;
        #pragma unroll
        for (int it = 0; it < 33; it++) {
            int i = tid + 512 * it;                 // 16640 = 32.5 * 512
            if (i < DP_ * MM2) {
                int d = i >> 8, mm = i & 255;       // MM2 = 256
                kvs[mm * 68 + d] = kvg[i];
            }
        }
        #pragma unroll
        for (int i = 0; i < 16; i++) {
            int idx = tid + 512 * i;
            wT[(idx & 63) * 132 + (idx >> 6)] = omega[idx];
        }
        const float4* xg = reinterpret_cast<const float4*>(query + ((size_t)b * T_ + t0) * F_);
        #pragma unroll
        for (int i = 0; i < 2; i++) {
            int idx = tid + 512 * i;                // 1024 float4
            int r = idx >> 4, c4 = idx & 15;
            *reinterpret_cast<float4*>(&xs[r * 68 + c4 * 4]) = xg[idx];
        }
    }
    __syncthreads();

    // ---- ss[r] = 0.5 * ||x_r||^2 ----
    if (tid < 64) {
        float p = 0.f;
        #pragma unroll
        for (int f = 0; f < 64; f++) { float v = xs[tid * 68 + f]; p += v * v; }
        ss[tid] = 0.5f * p;
    }
    __syncthreads();

    // ---- phase A: phi_q GEMM; warp w -> m-octet, lane -> rows lane, lane+32 ----
    {
        float a[2][8];
        #pragma unroll
        for (int jp = 0; jp < 2; jp++)
            #pragma unroll
            for (int c = 0; c < 8; c++) a[jp][c] = 0.f;

        const float* xr0 = &xs[lane * 68];
        const float* xr1 = &xs[(lane + 32) * 68];
        #pragma unroll
        for (int f0 = 0; f0 < 64; f0 += 4) {
            float4 xv0 = *reinterpret_cast<const float4*>(&xr0[f0]);
            float4 xv1 = *reinterpret_cast<const float4*>(&xr1[f0]);
            #pragma unroll
            for (int i = 0; i < 4; i++) {
                const float* wr = &wT[(f0 + i) * 132 + w * 8];
                float4 wa = *reinterpret_cast<const float4*>(wr);       // broadcast
                float4 wb = *reinterpret_cast<const float4*>(wr + 4);   // broadcast
                float x0 = (i == 0) ? xv0.x : (i == 1) ? xv0.y : (i == 2) ? xv0.z : xv0.w;
                float x1 = (i == 0) ? xv1.x : (i == 1) ? xv1.y : (i == 2) ? xv1.z : xv1.w;
                a[0][0] += x0 * wa.x; a[0][1] += x0 * wa.y;
                a[0][2] += x0 * wa.z; a[0][3] += x0 * wa.w;
                a[0][4] += x0 * wb.x; a[0][5] += x0 * wb.y;
                a[0][6] += x0 * wb.z; a[0][7] += x0 * wb.w;
                a[1][0] += x1 * wa.x; a[1][1] += x1 * wa.y;
                a[1][2] += x1 * wa.z; a[1][3] += x1 * wa.w;
                a[1][4] += x1 * wb.x; a[1][5] += x1 * wb.y;
                a[1][6] += x1 * wb.z; a[1][7] += x1 * wb.w;
            }
        }

        #pragma unroll
        for (int jp = 0; jp < 2; jp++) {
            int r = lane + jp * 32;
            float s = ss[r];
            float4 p1a, p1b, p2a, p2b;
            p1a.x = (__expf( a[jp][0] - s) + kEPS) * kSCALE;
            p1a.y = (__expf( a[jp][1] - s) + kEPS) * kSCALE;
            p1a.z = (__expf( a[jp][2] - s) + kEPS) * kSCALE;
            p1a.w = (__expf( a[jp][3] - s) + kEPS) * kSCALE;
            p1b.x = (__expf( a[jp][4] - s) + kEPS) * kSCALE;
            p1b.y = (__expf( a[jp][5] - s) + kEPS) * kSCALE;
            p1b.z = (__expf( a[jp][6] - s) + kEPS) * kSCALE;
            p1b.w = (__expf( a[jp][7] - s) + kEPS) * kSCALE;
            p2a.x = (__expf(-a[jp][0] - s) + kEPS) * kSCALE;
            p2a.y = (__expf(-a[jp][1] - s) + kEPS) * kSCALE;
            p2a.z = (__expf(-a[jp][2] - s) + kEPS) * kSCALE;
            p2a.w = (__expf(-a[jp][3] - s) + kEPS) * kSCALE;
            p2b.x = (__expf(-a[jp][4] - s) + kEPS) * kSCALE;
            p2b.y = (__expf(-a[jp][5] - s) + kEPS) * kSCALE;
            p2b.z = (__expf(-a[jp][6] - s) + kEPS) * kSCALE;
            p2b.w = (__expf(-a[jp][7] - s) + kEPS) * kSCALE;
            float* pr = &phis[r * 260 + w * 8];
            *reinterpret_cast<float4*>(pr)       = p1a;
            *reinterpret_cast<float4*>(pr + 4)   = p1b;
            *reinterpret_cast<float4*>(pr + 128) = p2a;
            *reinterpret_cast<float4*>(pr + 132) = p2b;
        }
    }
    __syncthreads();

    // ---- phase B: out = phi_q @ kv, normalized; thread owns 8 cols ----
    const int tt  = tid >> 3;
    const int p   = tid & 7;
    const int dof = p * 8;
    const float* ph = &phis[tt * 260];

    float4 a0 = make_float4(0.f, 0.f, 0.f, 0.f), a1 = a0;
    float anorm = 0.f;

    #pragma unroll 8
    for (int mm = 0; mm < MM2; mm++) {
        float f = ph[mm];
        const float* kr = &kvs[mm * 68 + dof];
        float4 k0 = *reinterpret_cast<const float4*>(kr);
        float4 k1 = *reinterpret_cast<const float4*>(kr + 4);
        a0.x += f * k0.x; a0.y += f * k0.y; a0.z += f * k0.z; a0.w += f * k0.w;
        a1.x += f * k1.x; a1.y += f * k1.y; a1.z += f * k1.z; a1.w += f * k1.w;
        if (p == 7) anorm += f * kvs[mm * 68 + 64];
    }

    if (p == 7) norm[tt] = anorm;
    __syncthreads();

    float inv = 1.0f / norm[tt];
    a0.x *= inv; a0.y *= inv; a0.z *= inv; a0.w *= inv;
    a1.x *= inv; a1.y *= inv; a1.z *= inv; a1.w *= inv;

    float4* og = reinterpret_cast<float4*>(out + ((size_t)b * T_ + t0 + tt) * D_ + dof);
    og[0] = a0; og[1] = a1;
}

// ======================= launch =======================
extern "C" void kernel_launch(void* const* d_in, const int* in_sizes, int n_in,
                              void* d_out, int out_size)
{
    const float* query = (const float*)d_in[0];
    const float* value = (const float*)d_in[1];
    const float* key   = (const float*)d_in[2];
    const float* omega = (const float*)d_in[3];
    float* out = (float*)d_out;

    cudaFuncSetAttribute(kv_fused,  cudaFuncAttributeMaxDynamicSharedMemorySize, KVF_SMEM);
    cudaFuncSetAttribute(qkv_fused, cudaFuncAttributeMaxDynamicSharedMemorySize, QF_SMEM);

    dim3 gkv(KV_CH, B_);
    kv_fused<<<gkv, 512, KVF_SMEM>>>(key, value, omega);
    reduce_kv<<<(KV_N4 + 255) / 256, 256>>>();

    dim3 gq(T_ / 64, B_);
    qkv_fused<<<gq, 512, QF_SMEM>>>(query, omega, out);
}

// round 9
// speedup vs baseline: 2.3601x; 2.3601x over previous
#include <cuda_runtime.h>
#include <math.h>

#define B_  8
#define T_  8192
#define F_  64
#define M_  128          // omega rows
#define MM2 256          // feature dim = 2*M
#define D_  64
#define DP_ 65           // D + 1 (normalizer column)

#define KV_CH    37      // grid 37*8 = 296 = one wave at 2 CTA/SM
#define KV_ROWS  224     // rows per chunk (37*224 = 8288 >= 8192, tail masked)

constexpr float kEPS   = 1e-9f;
constexpr float kSCALE = 0.0625f;  // 1/sqrt(2*128) = 1/16

// ---------------- device scratch (static, allocation-free) ----------------
// d-major partials: g_kvp[(cx*B+b)*DP*MM2 + d*MM2 + m]
__device__ float g_kvp[(size_t)KV_CH * B_ * DP_ * MM2];    // 19.7 MB
__device__ float g_kv [(size_t)B_ * DP_ * MM2];            // 0.53 MB

// ======================= Stage 1: kv_fused (phi_k + kv) =======================
// grid (KV_CH, B), block 512, 2 CTA/SM. Per 32-row step:
//   stage K/V -> phi GEMM (R5 mapping: omega per-lane LDS.128 conflict-free,
//   x broadcast) -> register-tiled accumulate (thread = 4m x 8d, 3 LDS / 32 FFMA).
#define KVF_WT   0                         // [64][132] omega^T padded
#define KVF_XS   (64 * 132)                // [32][68]
#define KVF_VS   (KVF_XS + 32 * 68)        // [32][68]
#define KVF_PHI  (KVF_VS + 32 * 68)        // [32][260]
#define KVF_SS   (KVF_PHI + 32 * 260)      // [32]
#define KVF_SMEM ((KVF_SS + 32) * 4)       // 84,608 B -> x2 = 169 KB/SM

__global__ void __launch_bounds__(512, 2) kv_fused(const float* __restrict__ key,
                                                   const float* __restrict__ value,
                                                   const float* __restrict__ omega)
{
    extern __shared__ float sm[];
    float* wT   = sm + KVF_WT;
    float* xs   = sm + KVF_XS;
    float* vs   = sm + KVF_VS;
    float* phis = sm + KVF_PHI;
    float* ss   = sm + KVF_SS;

    const int b   = blockIdx.y;
    const int cx  = blockIdx.x;
    const int s0  = cx * KV_ROWS;
    const int tid = threadIdx.x;

    // load omega transposed: wT[f][m], stride 132 (one-time)
    #pragma unroll
    for (int i = 0; i < 16; i++) {
        int idx = tid + 512 * i;               // 8192 floats, omega[m][f]
        wT[(idx & 63) * 132 + (idx >> 6)] = omega[idx];
    }

    // ---- roles ----
    const int wid = tid >> 5;      // warp 0..15: phi rows wid*2, wid*2+1
    const int tx  = tid & 31;      // phi m-quad
    const int lr  = tid >> 4;      // staging row 0..31
    const int lc  = tid & 15;      // staging float4 col
    const int mi  = tid & 63;      // accumulate m-quad (m = mi*4)
    const int di  = tid >> 6;      // accumulate d-octet (d = di*8)

    // register tile: acc[dd][mm] for d = di*8+dd, m = mi*4+mm; + normalizer
    float4 acc[8];
    #pragma unroll
    for (int q = 0; q < 8; q++) acc[q] = make_float4(0.f, 0.f, 0.f, 0.f);
    float4 accn = make_float4(0.f, 0.f, 0.f, 0.f);   // used by di==0 threads

    for (int sb = 0; sb < KV_ROWS; sb += 32) {
        const int sg = s0 + sb;
        __syncthreads();                       // prev accumulate done

        // ---- stage 32 key + 32 value rows; ss via 16-lane shfl ----
        {
            const int r = sg + lr;
            float4 xv = make_float4(0.f, 0.f, 0.f, 0.f);
            float4 vv = make_float4(0.f, 0.f, 0.f, 0.f);
            if (r < T_) {
                xv = *reinterpret_cast<const float4*>(key   + ((size_t)b * T_ + r) * F_ + lc * 4);
                vv = *reinterpret_cast<const float4*>(value + ((size_t)b * T_ + r) * D_ + lc * 4);
            }
            *reinterpret_cast<float4*>(&xs[lr * 68 + lc * 4]) = xv;
            *reinterpret_cast<float4*>(&vs[lr * 68 + lc * 4]) = vv;
            float p = xv.x * xv.x + xv.y * xv.y + xv.z * xv.z + xv.w * xv.w;
            p += __shfl_xor_sync(0xffffffffu, p, 8);
            p += __shfl_xor_sync(0xffffffffu, p, 4);
            p += __shfl_xor_sync(0xffffffffu, p, 2);
            p += __shfl_xor_sync(0xffffffffu, p, 1);
            if (lc == 0) ss[lr] = 0.5f * p;
        }
        __syncthreads();

        // ---- phi GEMM: warp wid -> rows wid*2, wid*2+1; lane tx -> m-quad ----
        {
            float a[2][4];
            #pragma unroll
            for (int jp = 0; jp < 2; jp++)
                #pragma unroll
                for (int c = 0; c < 4; c++) a[jp][c] = 0.f;

            #pragma unroll
            for (int f0 = 0; f0 < 64; f0 += 4) {
                float4 w0 = *reinterpret_cast<const float4*>(&wT[(f0 + 0) * 132 + tx * 4]);
                float4 w1 = *reinterpret_cast<const float4*>(&wT[(f0 + 1) * 132 + tx * 4]);
                float4 w2 = *reinterpret_cast<const float4*>(&wT[(f0 + 2) * 132 + tx * 4]);
                float4 w3 = *reinterpret_cast<const float4*>(&wT[(f0 + 3) * 132 + tx * 4]);
                #pragma unroll
                for (int jp = 0; jp < 2; jp++) {
                    float4 xv = *reinterpret_cast<const float4*>(&xs[(wid * 2 + jp) * 68 + f0]);
                    a[jp][0] += xv.x * w0.x + xv.y * w1.x + xv.z * w2.x + xv.w * w3.x;
                    a[jp][1] += xv.x * w0.y + xv.y * w1.y + xv.z * w2.y + xv.w * w3.y;
                    a[jp][2] += xv.x * w0.z + xv.y * w1.z + xv.z * w2.z + xv.w * w3.z;
                    a[jp][3] += xv.x * w0.w + xv.y * w1.w + xv.z * w2.w + xv.w * w3.w;
                }
            }
            #pragma unroll
            for (int jp = 0; jp < 2; jp++) {
                int r = wid * 2 + jp;
                float s  = ss[r];
                float sc = (sg + r < T_) ? kSCALE : 0.f;
                float4 p1, p2;
                p1.x = (__expf( a[jp][0] - s) + kEPS) * sc;
                p1.y = (__expf( a[jp][1] - s) + kEPS) * sc;
                p1.z = (__expf( a[jp][2] - s) + kEPS) * sc;
                p1.w = (__expf( a[jp][3] - s) + kEPS) * sc;
                p2.x = (__expf(-a[jp][0] - s) + kEPS) * sc;
                p2.y = (__expf(-a[jp][1] - s) + kEPS) * sc;
                p2.z = (__expf(-a[jp][2] - s) + kEPS) * sc;
                p2.w = (__expf(-a[jp][3] - s) + kEPS) * sc;
                *reinterpret_cast<float4*>(&phis[r * 260 + tx * 4])       = p1;
                *reinterpret_cast<float4*>(&phis[r * 260 + 128 + tx * 4]) = p2;
            }
        }
        __syncthreads();

        // ---- register-tiled accumulate: 3 LDS / 32 FFMA per j ----
        #pragma unroll 4
        for (int j = 0; j < 32; j++) {
            float4 ph = *reinterpret_cast<const float4*>(&phis[j * 260 + mi * 4]);   // conflict-free
            float4 va = *reinterpret_cast<const float4*>(&vs[j * 68 + di * 8]);      // broadcast
            float4 vb = *reinterpret_cast<const float4*>(&vs[j * 68 + di * 8 + 4]);  // broadcast
            acc[0].x += va.x * ph.x; acc[0].y += va.x * ph.y; acc[0].z += va.x * ph.z; acc[0].w += va.x * ph.w;
            acc[1].x += va.y * ph.x; acc[1].y += va.y * ph.y; acc[1].z += va.y * ph.z; acc[1].w += va.y * ph.w;
            acc[2].x += va.z * ph.x; acc[2].y += va.z * ph.y; acc[2].z += va.z * ph.z; acc[2].w += va.z * ph.w;
            acc[3].x += va.w * ph.x; acc[3].y += va.w * ph.y; acc[3].z += va.w * ph.z; acc[3].w += va.w * ph.w;
            acc[4].x += vb.x * ph.x; acc[4].y += vb.x * ph.y; acc[4].z += vb.x * ph.z; acc[4].w += vb.x * ph.w;
            acc[5].x += vb.y * ph.x; acc[5].y += vb.y * ph.y; acc[5].z += vb.y * ph.z; acc[5].w += vb.y * ph.w;
            acc[6].x += vb.z * ph.x; acc[6].y += vb.z * ph.y; acc[6].z += vb.z * ph.z; acc[6].w += vb.z * ph.w;
            acc[7].x += vb.w * ph.x; acc[7].y += vb.w * ph.y; acc[7].z += vb.w * ph.z; acc[7].w += vb.w * ph.w;
            if (di == 0) {
                accn.x += ph.x; accn.y += ph.y; accn.z += ph.z; accn.w += ph.w;
            }
        }
    }

    // ---- store d-major partials (coalesced float4 over m) ----
    const size_t slab = (size_t)(cx * B_ + b) * DP_;
    #pragma unroll
    for (int dd = 0; dd < 8; dd++)
        *reinterpret_cast<float4*>(&g_kvp[(slab + di * 8 + dd) * MM2 + mi * 4]) = acc[dd];
    if (di == 0)
        *reinterpret_cast<float4*>(&g_kvp[(slab + 64) * MM2 + mi * 4]) = accn;
}

// ======================= Stage 2: reduce partials (float4) =======================
#define KV_N4 (B_ * DP_ * MM2 / 4)   // 33280

__global__ void __launch_bounds__(256) reduce_kv()
{
    int i = blockIdx.x * blockDim.x + threadIdx.x;
    if (i < KV_N4) {
        const float4* src = reinterpret_cast<const float4*>(g_kvp);
        float4 s = make_float4(0.f, 0.f, 0.f, 0.f);
        #pragma unroll
        for (int c = 0; c < KV_CH; c++) {
            float4 v = src[(size_t)c * KV_N4 + i];
            s.x += v.x; s.y += v.y; s.z += v.z; s.w += v.w;
        }
        reinterpret_cast<float4*>(g_kv)[i] = s;
    }
}

// ======================= Stage 3: qkv_fused (phi_q + qkv + normalize) =======================
// grid (T/64, B), block 256. Phase A: phi_q (warp -> m-16-group, lane -> rows
// lane, lane+32; transposed conflict-free STS). Phase B: thread = 4r x 4c tile,
// 2 LDS / 16 FFMA per m.
#define QF_KVS  0                          // [256][68]  kv[m][d]
#define QF_WT   (256 * 68)                 // [64][132]
#define QF_XS   (QF_WT + 64 * 132)         // [64][68]
#define QF_PHT  (QF_XS + 64 * 68)          // [256][68]  phi^T[m][r]
#define QF_SS   (QF_PHT + 256 * 68)        // [64]
#define QF_NRM  (QF_SS + 64)               // [64]
#define QF_SMEM ((QF_NRM + 64) * 4)        // 190,976 B

__global__ void __launch_bounds__(256) qkv_fused(const float* __restrict__ query,
                                                 const float* __restrict__ omega,
                                                 float* __restrict__ out)
{
    extern __shared__ float sm[];
    float* kvs   = sm + QF_KVS;
    float* wT    = sm + QF_WT;
    float* xs    = sm + QF_XS;
    float* phisT = sm + QF_PHT;
    float* ss    = sm + QF_SS;
    float* norm  = sm + QF_NRM;

    const int b    = blockIdx.y;
    const int t0   = blockIdx.x * 64;
    const int tid  = threadIdx.x;
    const int wid  = tid >> 5;     // 0..7 -> m-16-group
    const int lane = tid & 31;

    // ---- loads: kv (d-major -> [m][d]), omega^T, query tile ----
    {
        const float* kvg = g_kv + (size_t)b * DP_ * MM2;
        #pragma unroll
        for (int it = 0; it < 65; it++) {
            int i = tid + 256 * it;                 // 16640 floats
            int d = i >> 8, mm = i & 255;
            kvs[mm * 68 + d] = kvg[i];
        }
        #pragma unroll
        for (int i = 0; i < 32; i++) {
            int idx = tid + 256 * i;
            wT[(idx & 63) * 132 + (idx >> 6)] = omega[idx];
        }
        const float4* xg = reinterpret_cast<const float4*>(query + ((size_t)b * T_ + t0) * F_);
        #pragma unroll
        for (int i = 0; i < 4; i++) {
            int idx = tid + 256 * i;                // 1024 float4
            int r = idx >> 4, c4 = idx & 15;
            *reinterpret_cast<float4*>(&xs[r * 68 + c4 * 4]) = xg[idx];
        }
    }
    __syncthreads();

    // ---- ss[r] = 0.5 * ||x_r||^2 ----
    if (tid < 64) {
        float p = 0.f;
        #pragma unroll
        for (int f = 0; f < 64; f++) { float v = xs[tid * 68 + f]; p += v * v; }
        ss[tid] = 0.5f * p;
    }
    __syncthreads();

    // ---- phase A: phi_q GEMM; warp wid -> m cols wid*16..+15, lane -> rows (lane, lane+32) ----
    {
        float a[2][16];
        #pragma unroll
        for (int jp = 0; jp < 2; jp++)
            #pragma unroll
            for (int c = 0; c < 16; c++) a[jp][c] = 0.f;

        const float* xr0 = &xs[lane * 68];            // per-lane stride 68: bank-clean
        const float* xr1 = &xs[(lane + 32) * 68];
        #pragma unroll 4
        for (int f0 = 0; f0 < 64; f0 += 4) {
            float4 xv0 = *reinterpret_cast<const float4*>(&xr0[f0]);
            float4 xv1 = *reinterpret_cast<const float4*>(&xr1[f0]);
            #pragma unroll
            for (int i = 0; i < 4; i++) {
                const float* wr = &wT[(f0 + i) * 132 + wid * 16];
                float4 wa = *reinterpret_cast<const float4*>(wr);        // broadcast
                float4 wb = *reinterpret_cast<const float4*>(wr + 4);
                float4 wc = *reinterpret_cast<const float4*>(wr + 8);
                float4 wd = *reinterpret_cast<const float4*>(wr + 12);
                float x0 = (i == 0) ? xv0.x : (i == 1) ? xv0.y : (i == 2) ? xv0.z : xv0.w;
                float x1 = (i == 0) ? xv1.x : (i == 1) ? xv1.y : (i == 2) ? xv1.z : xv1.w;
                a[0][0]  += x0 * wa.x; a[0][1]  += x0 * wa.y; a[0][2]  += x0 * wa.z; a[0][3]  += x0 * wa.w;
                a[0][4]  += x0 * wb.x; a[0][5]  += x0 * wb.y; a[0][6]  += x0 * wb.z; a[0][7]  += x0 * wb.w;
                a[0][8]  += x0 * wc.x; a[0][9]  += x0 * wc.y; a[0][10] += x0 * wc.z; a[0][11] += x0 * wc.w;
                a[0][12] += x0 * wd.x; a[0][13] += x0 * wd.y; a[0][14] += x0 * wd.z; a[0][15] += x0 * wd.w;
                a[1][0]  += x1 * wa.x; a[1][1]  += x1 * wa.y; a[1][2]  += x1 * wa.z; a[1][3]  += x1 * wa.w;
                a[1][4]  += x1 * wb.x; a[1][5]  += x1 * wb.y; a[1][6]  += x1 * wb.z; a[1][7]  += x1 * wb.w;
                a[1][8]  += x1 * wc.x; a[1][9]  += x1 * wc.y; a[1][10] += x1 * wc.z; a[1][11] += x1 * wc.w;
                a[1][12] += x1 * wd.x; a[1][13] += x1 * wd.y; a[1][14] += x1 * wd.z; a[1][15] += x1 * wd.w;
            }
        }

        // exp + transposed store: phisT[m][r], lane = r -> conflict-free STS.32
        #pragma unroll
        for (int jp = 0; jp < 2; jp++) {
            int r = lane + jp * 32;
            float s = ss[r];
            #pragma unroll
            for (int c = 0; c < 16; c++) {
                int m = wid * 16 + c;
                phisT[m * 68 + r]         = (__expf( a[jp][c] - s) + kEPS) * kSCALE;
                phisT[(128 + m) * 68 + r] = (__expf(-a[jp][c] - s) + kEPS) * kSCALE;
            }
        }
    }
    __syncthreads();

    // ---- phase B: out = phi_q @ kv; thread = 4 rows x 4 cols ----
    const int rg = tid & 15;       // rows rg*4..rg*4+3
    const int cg = tid >> 4;       // cols cg*4..cg*4+3

    float4 acc[4];
    #pragma unroll
    for (int rr = 0; rr < 4; rr++) acc[rr] = make_float4(0.f, 0.f, 0.f, 0.f);
    float4 anorm = make_float4(0.f, 0.f, 0.f, 0.f);

    #pragma unroll 4
    for (int m = 0; m < MM2; m++) {
        float4 ph = *reinterpret_cast<const float4*>(&phisT[m * 68 + rg * 4]);  // conflict-free
        float4 kv = *reinterpret_cast<const float4*>(&kvs[m * 68 + cg * 4]);    // ~broadcast
        acc[0].x += ph.x * kv.x; acc[0].y += ph.x * kv.y; acc[0].z += ph.x * kv.z; acc[0].w += ph.x * kv.w;
        acc[1].x += ph.y * kv.x; acc[1].y += ph.y * kv.y; acc[1].z += ph.y * kv.z; acc[1].w += ph.y * kv.w;
        acc[2].x += ph.z * kv.x; acc[2].y += ph.z * kv.y; acc[2].z += ph.z * kv.z; acc[2].w += ph.z * kv.w;
        acc[3].x += ph.w * kv.x; acc[3].y += ph.w * kv.y; acc[3].z += ph.w * kv.z; acc[3].w += ph.w * kv.w;
        if (cg == 0) {
            float kn = kvs[m * 68 + 64];
            anorm.x += ph.x * kn; anorm.y += ph.y * kn;
            anorm.z += ph.z * kn; anorm.w += ph.w * kn;
        }
    }

    if (cg == 0) {
        norm[rg * 4 + 0] = anorm.x;
        norm[rg * 4 + 1] = anorm.y;
        norm[rg * 4 + 2] = anorm.z;
        norm[rg * 4 + 3] = anorm.w;
    }
    __syncthreads();

    #pragma unroll
    for (int rr = 0; rr < 4; rr++) {
        float inv = 1.0f / norm[rg * 4 + rr];
        float4 o = make_float4(acc[rr].x * inv, acc[rr].y * inv,
                               acc[rr].z * inv, acc[rr].w * inv);
        *reinterpret_cast<float4*>(out + ((size_t)b * T_ + t0 + rg * 4 + rr) * D_ + cg * 4) = o;
    }
}

// ======================= launch =======================
extern "C" void kernel_launch(void* const* d_in, const int* in_sizes, int n_in,
                              void* d_out, int out_size)
{
    const float* query = (const float*)d_in[0];
    const float* value = (const float*)d_in[1];
    const float* key   = (const float*)d_in[2];
    const float* omega = (const float*)d_in[3];
    float* out = (float*)d_out;

    cudaFuncSetAttribute(kv_fused,  cudaFuncAttributeMaxDynamicSharedMemorySize, KVF_SMEM);
    cudaFuncSetAttribute(qkv_fused, cudaFuncAttributeMaxDynamicSharedMemorySize, QF_SMEM);

    dim3 gkv(KV_CH, B_);
    kv_fused<<<gkv, 512, KVF_SMEM>>>(key, value, omega);
    reduce_kv<<<(KV_N4 + 255) / 256, 256>>>();

    dim3 gq(T_ / 64, B_);
    qkv_fused<<<gq, 256, QF_SMEM>>>(query, omega, out);
}